// round 1
// baseline (speedup 1.0000x reference)
#include <cuda_runtime.h>
#include <cuda_bf16.h>

// Problem constants
#define B_SZ    2
#define L_SZ    4096
#define H_SZ    16
#define D_SZ    128
#define TILE_L  128
#define HALO    30                  // max kernel size - 1
#define SX_ROWS (TILE_L + HALO)     // 158
#define NTHREADS 512

// smem strides (floats)
#define SY_STRIDE 130
#define SW_STRIDE 129

#define SX_FLOATS (SX_ROWS * D_SZ)            // 20224
#define SY_FLOATS (TILE_L * SY_STRIDE)        // 16640
#define SW_FLOATS (D_SZ * SW_STRIDE)          // 16512
#define SMEM_FLOATS (SX_FLOATS + SY_FLOATS + SW_FLOATS)
#define SMEM_BYTES (SMEM_FLOATS * 4)          // 213,504 B

// Depthwise causal conv for one (kernel i, input head hh) slice.
// sy[rr][dd] = sum_{s=0}^{KK-1} sx[31-KK+rr+s][dd] * w[c][s]
// (tap-t form: out[l] = sum_t x[l-t] * w[c, KK-1-t], matching lax.conv with
//  left pad KK-1 and no kernel flip)
template <int KK>
__device__ __forceinline__ void conv_slice(const float* __restrict__ sx,
                                           float* __restrict__ sy,
                                           const float* __restrict__ wrow,
                                           int dd, int rbase)
{
    float wv[KK];
#pragma unroll
    for (int s = 0; s < KK; ++s) wv[s] = wrow[s];

#pragma unroll 4
    for (int r = 0; r < 32; ++r) {
        const int rr = rbase + r;
        float acc = 0.f;
        const float* xp = sx + (31 - KK + rr) * D_SZ + dd;
#pragma unroll
        for (int s = 0; s < KK; ++s)
            acc += xp[s * D_SZ] * wv[s];
        sy[rr * SY_STRIDE + dd] = acc;
    }
}

__global__ __launch_bounds__(NTHREADS, 1)
void dwmsconv_fused_kernel(const float* __restrict__ x,
                           const float* __restrict__ w1,
                           const float* __restrict__ w2,
                           const float* __restrict__ w3,
                           const float* __restrict__ w4,
                           const float* __restrict__ w5,
                           const float* __restrict__ w_mix,
                           float* __restrict__ out)
{
    extern __shared__ float smem[];
    float* sx = smem;                    // [SX_ROWS][128]
    float* sy = sx + SX_FLOATS;          // [TILE_L][SY_STRIDE]
    float* sw = sy + SY_FLOATS;          // [128 k][SW_STRIDE] (transposed w_mix slice)

    const int tid  = threadIdx.x;
    const int warp = tid >> 5;           // 0..15
    const int lane = tid & 31;

    const int l0 = blockIdx.x * TILE_L;
    const int hp = blockIdx.y;           // output head h'
    const int b  = blockIdx.z;

    // GEMM micro-tile: rows warp*8 .. +7 (warp-uniform), cols lane + 32*jj
    const int row_base = warp * 8;
    const int col_base = lane;

    float acc[8][4];
#pragma unroll
    for (int r = 0; r < 8; ++r)
#pragma unroll
        for (int c = 0; c < 4; ++c) acc[r][c] = 0.f;

    // conv-phase mapping: dd = tid & 127, 32 rows per thread
    const int cdd    = tid & (D_SZ - 1);
    const int crbase = (tid >> 7) * 32;  // 0,32,64,96

    for (int j = 0; j < 5; ++j) {
        const int g  = 5 * hp + j;       // 0..79
        const int ki = g >> 4;           // conv kernel index 0..4
        const int hh = g & 15;           // input head

        __syncthreads();                 // previous-iter smem reads done

        // ---- load x tile (with causal halo; rows < 0 are zero) ----
        {
            const float* xbase = x + ((long long)b * L_SZ) * (H_SZ * D_SZ) + hh * D_SZ;
            for (int idx = tid; idx < SX_ROWS * 32; idx += NTHREADS) {
                const int r  = idx >> 5;
                const int c4 = idx & 31;
                const int l  = l0 - HALO + r;
                float4 v;
                if (l >= 0) {
                    v = *(const float4*)(xbase + (long long)l * (H_SZ * D_SZ) + c4 * 4);
                } else {
                    v = make_float4(0.f, 0.f, 0.f, 0.f);
                }
                *(float4*)(sx + r * D_SZ + c4 * 4) = v;
            }
        }

        // ---- load w_mix slice transposed: sw[k][d] = w_mix[d][j*128 + k] ----
        {
#pragma unroll
            for (int v = 0; v < 8; ++v) {
                const int d = warp + 16 * v;                 // 0..127
                const float4 val = *(const float4*)(w_mix + d * 640 + j * 128 + lane * 4);
                sw[(lane * 4 + 0) * SW_STRIDE + d] = val.x;
                sw[(lane * 4 + 1) * SW_STRIDE + d] = val.y;
                sw[(lane * 4 + 2) * SW_STRIDE + d] = val.z;
                sw[(lane * 4 + 3) * SW_STRIDE + d] = val.w;
            }
        }

        __syncthreads();

        // ---- depthwise conv into sy ----
        {
            const int c = hh * D_SZ + cdd;
            switch (ki) {
                case 0: conv_slice<1 >(sx, sy, w1 + c * 1,  cdd, crbase); break;
                case 1: conv_slice<3 >(sx, sy, w2 + c * 3,  cdd, crbase); break;
                case 2: conv_slice<7 >(sx, sy, w3 + c * 7,  cdd, crbase); break;
                case 3: conv_slice<15>(sx, sy, w4 + c * 15, cdd, crbase); break;
                default: conv_slice<31>(sx, sy, w5 + c * 31, cdd, crbase); break;
            }
        }

        __syncthreads();

        // ---- GEMM: acc[r][c] += sy[row][k] * sw[k][col] over k=0..127 ----
#pragma unroll 4
        for (int k = 0; k < 128; ++k) {
            float a[8];
#pragma unroll
            for (int r = 0; r < 8; ++r)
                a[r] = sy[(row_base + r) * SY_STRIDE + k];   // warp-uniform broadcast
            float bb[4];
#pragma unroll
            for (int c = 0; c < 4; ++c)
                bb[c] = sw[k * SW_STRIDE + col_base + 32 * c]; // bank-distinct
#pragma unroll
            for (int r = 0; r < 8; ++r)
#pragma unroll
                for (int c = 0; c < 4; ++c)
                    acc[r][c] += a[r] * bb[c];
        }
    }

    // ---- epilogue: out[b][l0+row][hp][d] ----
#pragma unroll
    for (int r = 0; r < 8; ++r) {
        const int row = row_base + r;
        float* op = out + (((long long)b * L_SZ + l0 + row) * H_SZ + hp) * D_SZ;
#pragma unroll
        for (int c = 0; c < 4; ++c)
            op[col_base + 32 * c] = acc[r][c];
    }
}

extern "C" void kernel_launch(void* const* d_in, const int* in_sizes, int n_in,
                              void* d_out, int out_size)
{
    const float* x     = (const float*)d_in[0];
    const float* w1    = (const float*)d_in[1];
    const float* w2    = (const float*)d_in[2];
    const float* w3    = (const float*)d_in[3];
    const float* w4    = (const float*)d_in[4];
    const float* w5    = (const float*)d_in[5];
    const float* w_mix = (const float*)d_in[6];
    float* out = (float*)d_out;

    cudaFuncSetAttribute(dwmsconv_fused_kernel,
                         cudaFuncAttributeMaxDynamicSharedMemorySize, SMEM_BYTES);

    dim3 grid(L_SZ / TILE_L, H_SZ, B_SZ);   // (32, 16, 2)
    dwmsconv_fused_kernel<<<grid, NTHREADS, SMEM_BYTES>>>(
        x, w1, w2, w3, w4, w5, w_mix, out);
}

// round 3
// speedup vs baseline: 1.2749x; 1.2749x over previous
#include <cuda_runtime.h>
#include <cuda_bf16.h>

// Problem constants
#define B_SZ    2
#define L_SZ    4096
#define H_SZ    16
#define D_SZ    128
#define TILE_L  128
#define HALO    30                  // max kernel size - 1
#define SX_ROWS (TILE_L + HALO)     // 158
#define NTHREADS 512

// smem strides (floats)
#define SYT_STRIDE 132              // syT[k][row], mult-of-4 (aligned float4), 16B*lane phase-distinct
#define SW_STRIDE  132              // sw[d][k],   same properties

#define SX_FLOATS (SX_ROWS * D_SZ)            // 20224
#define SYT_FLOATS (D_SZ * SYT_STRIDE)        // 16896
#define SW_FLOATS (D_SZ * SW_STRIDE)          // 16896
#define SMEM_FLOATS (SX_FLOATS + SYT_FLOATS + SW_FLOATS)
#define SMEM_BYTES (SMEM_FLOATS * 4)          // 216,064 B

typedef unsigned long long u64;

// ---- packed fp32x2 helpers (Blackwell FFMA2 — only reachable via PTX) ----
__device__ __forceinline__ void ffma2(u64& d, u64 a, u64 b) {
    asm("fma.rn.f32x2 %0, %1, %2, %0;" : "+l"(d) : "l"(a), "l"(b));
}
__device__ __forceinline__ u64 pack_dup(float x) {
    u64 r;
    asm("mov.b64 %0, {%1, %1};" : "=l"(r) : "f"(x));
    return r;
}
__device__ __forceinline__ void unpack2(u64 v, float& lo, float& hi) {
    asm("mov.b64 {%0, %1}, %2;" : "=f"(lo), "=f"(hi) : "l"(v));
}

// Depthwise causal conv for one (kernel K, input head) slice, writing the
// TRANSPOSED tile syT[k=dd][row].
// syT[dd][rr] = sum_{s=0}^{KK-1} sx[31-KK+rr+s][dd] * w[c][s]
// (tap form out[l] = sum_t x[l-t] * w[c, KK-1-t] — matches lax.conv, verified R1)
template <int KK>
__device__ __forceinline__ void conv_slice(const float* __restrict__ sx,
                                           float* __restrict__ syT,
                                           const float* __restrict__ wrow,
                                           int dd, int rbase)
{
    float wv[KK];
#pragma unroll
    for (int s = 0; s < KK; ++s) wv[s] = wrow[s];

#pragma unroll
    for (int rb4 = 0; rb4 < 32; rb4 += 4) {
        const int rr = rbase + rb4;
        float a0 = 0.f, a1 = 0.f, a2 = 0.f, a3 = 0.f;
#pragma unroll
        for (int s = 0; s < KK; ++s) {
            const float* xp = sx + (31 - KK + rr + s) * D_SZ + dd;
            a0 += xp[0 * D_SZ] * wv[s];
            a1 += xp[1 * D_SZ] * wv[s];
            a2 += xp[2 * D_SZ] * wv[s];
            a3 += xp[3 * D_SZ] * wv[s];
        }
        *(float4*)(syT + dd * SYT_STRIDE + rr) = make_float4(a0, a1, a2, a3);
    }
}

__global__ __launch_bounds__(NTHREADS, 1)
void dwmsconv_fused_kernel(const float* __restrict__ x,
                           const float* __restrict__ w1,
                           const float* __restrict__ w2,
                           const float* __restrict__ w3,
                           const float* __restrict__ w4,
                           const float* __restrict__ w5,
                           const float* __restrict__ w_mix,
                           float* __restrict__ out)
{
    extern __shared__ float smem[];
    float* sx  = smem;                   // [SX_ROWS][128]
    float* syT = sx + SX_FLOATS;         // [128 k][SYT_STRIDE] -> syT[dd][row]
    float* sw  = syT + SYT_FLOATS;       // [128 d][SW_STRIDE]  -> w_mix natural layout

    const int tid  = threadIdx.x;
    const int warp = tid >> 5;           // 0..15
    const int lane = tid & 31;

    const int l0 = blockIdx.x * TILE_L;
    const int hp = blockIdx.y;           // output head h'
    const int b  = blockIdx.z;

    // GEMM micro-tile: rows warp*8 .. +7 (warp-uniform), cols lane + 32*c
    const int rb = warp * 8;

    // acc[rp][c] packs rows (rb+2rp, rb+2rp+1) for column lane+32c
    u64 acc[4][4];
#pragma unroll
    for (int rp = 0; rp < 4; ++rp)
#pragma unroll
        for (int c = 0; c < 4; ++c) acc[rp][c] = 0ull;

    // conv-phase mapping: dd = tid & 127, 32 rows per thread
    const int cdd    = tid & (D_SZ - 1);
    const int crbase = (tid >> 7) * 32;  // 0,32,64,96

    for (int j = 0; j < 5; ++j) {
        const int g  = 5 * hp + j;       // 0..79
        const int ki = g >> 4;           // conv kernel index 0..4
        const int hh = g & 15;           // input head

        __syncthreads();                 // previous-iter smem reads done

        // ---- load x tile (with causal halo; rows < 0 are zero) ----
        {
            const float* xbase = x + ((long long)b * L_SZ) * (H_SZ * D_SZ) + hh * D_SZ;
            for (int idx = tid; idx < SX_ROWS * 32; idx += NTHREADS) {
                const int r  = idx >> 5;
                const int c4 = idx & 31;
                const int l  = l0 - HALO + r;
                float4 v;
                if (l >= 0) {
                    v = *(const float4*)(xbase + (long long)l * (H_SZ * D_SZ) + c4 * 4);
                } else {
                    v = make_float4(0.f, 0.f, 0.f, 0.f);
                }
                *(float4*)(sx + r * D_SZ + c4 * 4) = v;
            }
        }

        // ---- load w_mix slice, natural layout: sw[d][k] = w_mix[d][j*128+k] ----
        {
#pragma unroll
            for (int v = 0; v < 8; ++v) {
                const int d = warp + 16 * v;                 // 0..127
                const float4 val = *(const float4*)(w_mix + d * 640 + j * 128 + lane * 4);
                *(float4*)(sw + d * SW_STRIDE + lane * 4) = val;  // coalesced, conflict-free
            }
        }

        __syncthreads();

        // ---- depthwise conv into syT (transposed) ----
        {
            const int c = hh * D_SZ + cdd;
            switch (ki) {
                case 0: conv_slice<1 >(sx, syT, w1 + c * 1,  cdd, crbase); break;
                case 1: conv_slice<3 >(sx, syT, w2 + c * 3,  cdd, crbase); break;
                case 2: conv_slice<7 >(sx, syT, w3 + c * 7,  cdd, crbase); break;
                case 3: conv_slice<15>(sx, syT, w4 + c * 15, cdd, crbase); break;
                default: conv_slice<31>(sx, syT, w5 + c * 31, cdd, crbase); break;
            }
        }

        __syncthreads();

        // ---- GEMM with packed fp32x2 FMAs ----
        // acc[rp][c] += syT[k][rb+2rp .. +1] * sw[lane+32c][k]
#pragma unroll 2
        for (int k4 = 0; k4 < 128; k4 += 4) {
            // B: float4 along k per column (LDS.128, 16B*lane -> conflict-free)
            float4 bq[4];
#pragma unroll
            for (int c = 0; c < 4; ++c)
                bq[c] = *(const float4*)(sw + (lane + 32 * c) * SW_STRIDE + k4);

#pragma unroll
            for (int kk = 0; kk < 4; ++kk) {
                const float* syk = syT + (k4 + kk) * SYT_STRIDE + rb;
                // A: row pairs as broadcast LDS.64
                u64 a0 = *(const u64*)(syk + 0);
                u64 a1 = *(const u64*)(syk + 2);
                u64 a2 = *(const u64*)(syk + 4);
                u64 a3 = *(const u64*)(syk + 6);

                const float* bqp0 = (const float*)&bq[0];
                const float* bqp1 = (const float*)&bq[1];
                const float* bqp2 = (const float*)&bq[2];
                const float* bqp3 = (const float*)&bq[3];
                u64 b0 = pack_dup(bqp0[kk]);
                u64 b1 = pack_dup(bqp1[kk]);
                u64 b2 = pack_dup(bqp2[kk]);
                u64 b3 = pack_dup(bqp3[kk]);

                ffma2(acc[0][0], a0, b0); ffma2(acc[0][1], a0, b1);
                ffma2(acc[0][2], a0, b2); ffma2(acc[0][3], a0, b3);
                ffma2(acc[1][0], a1, b0); ffma2(acc[1][1], a1, b1);
                ffma2(acc[1][2], a1, b2); ffma2(acc[1][3], a1, b3);
                ffma2(acc[2][0], a2, b0); ffma2(acc[2][1], a2, b1);
                ffma2(acc[2][2], a2, b2); ffma2(acc[2][3], a2, b3);
                ffma2(acc[3][0], a3, b0); ffma2(acc[3][1], a3, b1);
                ffma2(acc[3][2], a3, b2); ffma2(acc[3][3], a3, b3);
            }
        }
    }

    // ---- epilogue: out[b][l0+row][hp][d] ----
#pragma unroll
    for (int rp = 0; rp < 4; ++rp) {
        const int row0 = rb + 2 * rp;
        float* op0 = out + (((long long)b * L_SZ + l0 + row0    ) * H_SZ + hp) * D_SZ;
        float* op1 = out + (((long long)b * L_SZ + l0 + row0 + 1) * H_SZ + hp) * D_SZ;
#pragma unroll
        for (int c = 0; c < 4; ++c) {
            float lo, hi;
            unpack2(acc[rp][c], lo, hi);
            op0[lane + 32 * c] = lo;
            op1[lane + 32 * c] = hi;
        }
    }
}

extern "C" void kernel_launch(void* const* d_in, const int* in_sizes, int n_in,
                              void* d_out, int out_size)
{
    const float* x     = (const float*)d_in[0];
    const float* w1    = (const float*)d_in[1];
    const float* w2    = (const float*)d_in[2];
    const float* w3    = (const float*)d_in[3];
    const float* w4    = (const float*)d_in[4];
    const float* w5    = (const float*)d_in[5];
    const float* w_mix = (const float*)d_in[6];
    float* out = (float*)d_out;

    cudaFuncSetAttribute(dwmsconv_fused_kernel,
                         cudaFuncAttributeMaxDynamicSharedMemorySize, SMEM_BYTES);

    dim3 grid(L_SZ / TILE_L, H_SZ, B_SZ);   // (32, 16, 2)
    dwmsconv_fused_kernel<<<grid, NTHREADS, SMEM_BYTES>>>(
        x, w1, w2, w3, w4, w5, w_mix, out);
}